// round 8
// baseline (speedup 1.0000x reference)
#include <cuda_runtime.h>

#define BB 8
#define TT 4096
#define DD 256
#define HH 256
#define G4 1024   // 4*H
#define CLUS 8
#define NTHR 512

// 128 MB scratch for x@Wi+b, [B*T, 4H]
__device__ float g_xWi[BB * TT * G4];

// ---------------------------------------------------------------------------
// GEMM: g_xWi = x[B*T, D] @ Wi[D, 4H] + b
// ---------------------------------------------------------------------------
__global__ void __launch_bounds__(256) gemm_kernel(const float* __restrict__ x,
                                                   const float* __restrict__ Wi,
                                                   const float* __restrict__ bias) {
    __shared__ float As[16][132];
    __shared__ float Bs[16][64];

    int tid = threadIdx.x;
    int bm = blockIdx.y, bn = blockIdx.x;
    const float* Ablk = x + (size_t)bm * 128 * DD;
    const float* Bblk = Wi + bn * 64;

    int ty = tid >> 4;
    int tx = tid & 15;

    float acc[8][4];
#pragma unroll
    for (int i = 0; i < 8; i++)
#pragma unroll
        for (int j = 0; j < 4; j++) acc[i][j] = 0.f;

    for (int k0 = 0; k0 < DD; k0 += 16) {
#pragma unroll
        for (int i = 0; i < 2; i++) {
            int f4  = tid * 2 + i;
            int row = f4 >> 2;
            int kq  = (f4 & 3) * 4;
            float4 v = *(const float4*)(Ablk + (size_t)row * DD + k0 + kq);
            As[kq + 0][row] = v.x;
            As[kq + 1][row] = v.y;
            As[kq + 2][row] = v.z;
            As[kq + 3][row] = v.w;
        }
        {
            int kk = tid >> 4;
            int nc = (tid & 15) * 4;
            *(float4*)&Bs[kk][nc] =
                *(const float4*)(Bblk + (size_t)(k0 + kk) * G4 + nc);
        }
        __syncthreads();

#pragma unroll
        for (int kk = 0; kk < 16; kk++) {
            float a[8], bb[4];
            *(float4*)(a)     = *(float4*)&As[kk][ty * 8];
            *(float4*)(a + 4) = *(float4*)&As[kk][ty * 8 + 4];
            *(float4*)(bb)    = *(float4*)&Bs[kk][tx * 4];
#pragma unroll
            for (int i = 0; i < 8; i++)
#pragma unroll
                for (int j = 0; j < 4; j++) acc[i][j] += a[i] * bb[j];
        }
        __syncthreads();
    }

    int col = bn * 64 + tx * 4;
    float4 bv = *(const float4*)(bias + col);
#pragma unroll
    for (int i = 0; i < 8; i++) {
        int row = bm * 128 + ty * 8 + i;
        float4 o;
        o.x = acc[i][0] + bv.x;
        o.y = acc[i][1] + bv.y;
        o.z = acc[i][2] + bv.z;
        o.w = acc[i][3] + bv.w;
        *(float4*)(g_xWi + (size_t)row * G4 + col) = o;
    }
}

// ---------------------------------------------------------------------------
// mbarrier helpers
// ---------------------------------------------------------------------------
__device__ __forceinline__ void mbar_arrive_peer(unsigned int local_mbar, int rank) {
    asm volatile(
        "{\n\t"
        ".reg .b32 ra;\n\t"
        "mapa.shared::cluster.u32 ra, %0, %1;\n\t"
        "mbarrier.arrive.release.cluster.shared::cluster.b64 _, [ra];\n\t"
        "}"
        :: "r"(local_mbar), "r"(rank) : "memory");
}

__device__ __forceinline__ void mbar_wait(unsigned int mbar, unsigned int parity) {
    asm volatile(
        "{\n\t"
        ".reg .pred P;\n\t"
        "WAIT_%=:\n\t"
        "mbarrier.try_wait.parity.acquire.cluster.shared::cta.b64 P, [%0], %1, 0x989680;\n\t"
        "@P bra.uni DONE_%=;\n\t"
        "bra.uni WAIT_%=;\n\t"
        "DONE_%=:\n\t"
        "}"
        :: "r"(mbar), "r"(parity) : "memory");
}

// ---------------------------------------------------------------------------
// Recurrent kernel: 1 cluster (8 CTAs) per batch; grid = 64 CTAs of 512 thr.
// Compute phase (16 warps): warp w reduces 8 gate columns for h-indices
// 2w, 2w+1 of its CTA's 32-index slice; lane owns a d-chunk of 8 (Wh in regs
// as packed f32x2). Full-split butterfly leaves column (l>>2)&7 on lane l;
// lanes with (l&3)==0 STS the sums to v_s. Gate phase (warp 0, 32 lanes):
// lane k owns h-index r*32+k -> LDS.128 sums, gate math, DSMEM broadcast of
// new h to all 8 CTAs, remote release-arrives, coalesced y STG.
// Step sync: PING-PONG mbarriers mbar[t&1] (count 8 = one arrive per source
// CTA), parity (t>>1)&1. Two barriers are required: a CTA may run one step
// ahead, and its next arrival must not pollute a peer's still-counting
// phase (mbarrier arrivals are not phase-tagged). With ping-pong, reuse of
// mbar[i] is gated by a wait that transitively requires every CTA to have
// flipped that barrier. No remote op on the last step (peer-exit race).
// ---------------------------------------------------------------------------
__global__ void __launch_bounds__(NTHR, 1) __cluster_dims__(CLUS, 1, 1)
rnn_kernel(const float* __restrict__ Wh,
           const int* __restrict__ seqlen,
           float* __restrict__ y) {
    __shared__ float  h_s[2][HH];
    __shared__ float4 v_s[32];                       // (i,f,g,o) sums per h
    __shared__ __align__(16) unsigned long long mbar[2];

    const int b = blockIdx.x / CLUS;
    const int r = blockIdx.x % CLUS;
    const int w = threadIdx.x >> 5;
    const int l = threadIdx.x & 31;
    const int k0 = r * 32 + 2 * w;

    // ---- preload Wh slice as packed f32x2 pairs over d ----
    unsigned long long wh2[8][4];
#pragma unroll
    for (int j = 0; j < 8; j++) {
        int col = (j < 4) ? (k0 + 256 * j) : (k0 + 1 + 256 * (j - 4));
#pragma unroll
        for (int dd = 0; dd < 4; dd++) {
            int d = l * 8 + dd * 2;
            float lo = Wh[(size_t)d * G4 + col];
            float hi = Wh[(size_t)(d + 1) * G4 + col];
            asm("mov.b64 %0, {%1, %2};" : "=l"(wh2[j][dd]) : "f"(lo), "f"(hi));
        }
    }

    // ---- init: zero h buffer 0, init both mbars; cluster-sync once ----
    for (int i = threadIdx.x; i < HH; i += NTHR) h_s[0][i] = 0.f;
    unsigned int mbar_base;
    asm("{ .reg .u64 t; cvta.to.shared.u64 t, %1; cvt.u32.u64 %0, t; }"
        : "=r"(mbar_base) : "l"((void*)mbar));
    if (threadIdx.x == 0) {
        asm volatile("mbarrier.init.shared.b64 [%0], %1;"
                     :: "r"(mbar_base), "r"((unsigned)CLUS) : "memory");
        asm volatile("mbarrier.init.shared.b64 [%0], %1;"
                     :: "r"(mbar_base + 8u), "r"((unsigned)CLUS) : "memory");
    }
    __syncthreads();
    asm volatile("barrier.cluster.arrive.aligned;" ::: "memory");
    asm volatile("barrier.cluster.wait.aligned;"   ::: "memory");

    const int L = seqlen[b];
    const float* xWib = g_xWi + (size_t)b * TT * G4;
    float*       yb   = y + (size_t)b * TT * HH;

    // ---- warp-0 per-lane gate state ----
    const int myk = r * 32 + l;
    float c_state = 0.f;

    // DSMEM peer addresses for h slot myk (buffer 0)
    unsigned int hs_addr;
    asm("{ .reg .u64 t; cvta.to.shared.u64 t, %1; cvt.u32.u64 %0, t; }"
        : "=r"(hs_addr) : "l"((void*)h_s));
    unsigned int slot0 = hs_addr + (unsigned)myk * 4u;
    unsigned int peer[CLUS];
#pragma unroll
    for (int p = 0; p < CLUS; p++)
        asm("mapa.shared::cluster.u32 %0, %1, %2;"
            : "=r"(peer[p]) : "r"(slot0), "r"(p));

    // warp0: preload xWi gates for t=0 (4 coalesced 128B loads)
    float xc0 = 0.f, xc1 = 0.f, xc2 = 0.f, xc3 = 0.f;
    if (w == 0) {
        int src0 = (TT - 1 + L) & (TT - 1);
        const float* p = xWib + (size_t)src0 * G4 + myk;
        xc0 = p[0]; xc1 = p[256]; xc2 = p[512]; xc3 = p[768];
    }

    const int cidx = (l >> 2) & 7;              // column after butterfly
    const int h_local = 2 * w + (cidx >> 2);
    const int gate    = cidx & 3;
    const bool storer = ((l & 3) == 0);

    for (int t = 0; t < TT; t++) {
        // warp0: prefetch next step's xWi (consumed next iteration)
        float xn0 = 0.f, xn1 = 0.f, xn2 = 0.f, xn3 = 0.f;
        if (w == 0 && t + 1 < TT) {
            int srcn = (TT - 2 - t + L) & (TT - 1);
            const float* p = xWib + (size_t)srcn * G4 + myk;
            xn0 = p[0]; xn1 = p[256]; xn2 = p[512]; xn3 = p[768];
        }

        // load previous h (own SMEM) as packed pairs
        const unsigned long long* hp =
            (const unsigned long long*)&h_s[t & 1][l * 8];
        unsigned long long h2[4];
        h2[0] = hp[0]; h2[1] = hp[1]; h2[2] = hp[2]; h2[3] = hp[3];

        // 8 packed-f32x2 accumulators (one per gate column)
        unsigned long long acc[8];
#pragma unroll
        for (int j = 0; j < 8; j++) acc[j] = 0ull;
#pragma unroll
        for (int dd = 0; dd < 4; dd++)
#pragma unroll
            for (int j = 0; j < 8; j++)
                asm("fma.rn.f32x2 %0, %1, %2, %0;"
                    : "+l"(acc[j]) : "l"(h2[dd]), "l"(wh2[j][dd]));

        // horizontal pair-sum -> ps[8]
        float ps[8];
#pragma unroll
        for (int j = 0; j < 8; j++) {
            float lo, hi;
            asm("mov.b64 {%0, %1}, %2;" : "=f"(lo), "=f"(hi) : "l"(acc[j]));
            ps[j] = lo + hi;
        }

        // full-split butterfly: 16 SHFL, 5 levels
        float u0, u1, u2, u3;
        {
            float a0 = __shfl_xor_sync(0xffffffffu, ps[0], 16);
            float a4 = __shfl_xor_sync(0xffffffffu, ps[4], 16);
            float a1 = __shfl_xor_sync(0xffffffffu, ps[1], 16);
            float a5 = __shfl_xor_sync(0xffffffffu, ps[5], 16);
            float a2 = __shfl_xor_sync(0xffffffffu, ps[2], 16);
            float a6 = __shfl_xor_sync(0xffffffffu, ps[6], 16);
            float a3 = __shfl_xor_sync(0xffffffffu, ps[3], 16);
            float a7 = __shfl_xor_sync(0xffffffffu, ps[7], 16);
            bool hi = (l & 16);
            u0 = hi ? (ps[4] + a4) : (ps[0] + a0);
            u1 = hi ? (ps[5] + a5) : (ps[1] + a1);
            u2 = hi ? (ps[6] + a6) : (ps[2] + a2);
            u3 = hi ? (ps[7] + a7) : (ps[3] + a3);
        }
        float t0, t1;
        {
            float a0 = __shfl_xor_sync(0xffffffffu, u0, 8);
            float a2 = __shfl_xor_sync(0xffffffffu, u2, 8);
            float a1 = __shfl_xor_sync(0xffffffffu, u1, 8);
            float a3 = __shfl_xor_sync(0xffffffffu, u3, 8);
            bool hi = (l & 8);
            t0 = hi ? (u2 + a2) : (u0 + a0);
            t1 = hi ? (u3 + a3) : (u1 + a1);
        }
        float s;
        {
            float a0 = __shfl_xor_sync(0xffffffffu, t0, 4);
            float a1 = __shfl_xor_sync(0xffffffffu, t1, 4);
            s = (l & 4) ? (t1 + a1) : (t0 + a0);
        }
        s += __shfl_xor_sync(0xffffffffu, s, 2);
        s += __shfl_xor_sync(0xffffffffu, s, 1);

        if (storer) ((float*)&v_s[h_local])[gate] = s;
        __syncthreads();

        const unsigned int step_mbar = mbar_base + (unsigned)(t & 1) * 8u;

        if (w == 0) {
            float4 vv = v_s[l];
            float zi = vv.x + xc0;
            float zf = vv.y + xc1;
            float zg = vv.z + xc2;
            float zo = vv.w + xc3;
            float si = 1.f / (1.f + __expf(-zi));
            float sf = 1.f / (1.f + __expf(-zf));
            float so = 1.f / (1.f + __expf(-zo));
            float tg = 2.f / (1.f + __expf(-2.f * zg)) - 1.f;
            c_state  = sf * c_state + si * tg;
            float tc = 2.f / (1.f + __expf(-2.f * c_state)) - 1.f;
            float nh = so * tc;

            if (t < TT - 1) {
                // broadcast new h to every CTA, then release-arrive on each
                // peer's step mbar (lane p -> peer p). Never on last step.
                unsigned int bufoff = ((t + 1) & 1) ? (unsigned)HH * 4u : 0u;
#pragma unroll
                for (int p = 0; p < CLUS; p++)
                    asm volatile("st.shared::cluster.f32 [%0], %1;"
                                 :: "r"(peer[p] + bufoff), "f"(nh) : "memory");
                __syncwarp();
                if (l < CLUS) mbar_arrive_peer(step_mbar, l);
            }

            const int src = (TT - 1 - t + L) & (TT - 1);
            yb[(size_t)src * HH + myk] = nh;   // coalesced 128B store

            xc0 = xn0; xc1 = xn1; xc2 = xn2; xc3 = xn3;
        }

        if (t < TT - 1) mbar_wait(step_mbar, (unsigned)((t >> 1) & 1));
    }
}

// ---------------------------------------------------------------------------
extern "C" void kernel_launch(void* const* d_in, const int* in_sizes, int n_in,
                              void* d_out, int out_size) {
    const float* x    = (const float*)d_in[0];
    const float* Wi   = (const float*)d_in[1];
    const float* Wh   = (const float*)d_in[2];
    const float* bias = (const float*)d_in[3];
    const int*   seql = (const int*)d_in[4];
    float*       y    = (float*)d_out;

    gemm_kernel<<<dim3(G4 / 64, (BB * TT) / 128), 256>>>(x, Wi, bias);
    rnn_kernel<<<BB * CLUS, NTHR>>>(Wh, seql, y);
}